// round 5
// baseline (speedup 1.0000x reference)
#include <cuda_runtime.h>
#include <cuda_fp16.h>

#define NMAX 100000
#define EMAX 3200000
#define GMAXG 256
#define IN_DIM 25

// Scratch
__device__ float  g_bufA[NMAX * 64];
__device__ float  g_bufC[NMAX * 64];
__device__ __half g_hbuf[NMAX * 64];   // half-precision pull inputs (xh / h1 / T)
__device__ int2   g_csr[EMAX];         // {src, weight-bits} grouped by dst
__device__ int    g_rowptr[NMAX + 2];
__device__ int    g_len[NMAX + 1];
__device__ int    g_cur[NMAX + 1];
__device__ int    g_bsum[512];
__device__ float  g_dinv[NMAX];
__device__ float  g_pool[GMAXG * 32];
__device__ int    g_cnt[GMAXG];

// ---------------- init: zero len + pool + cnt ----------------
__global__ void k_init(int n1, int G) {
    int i = blockIdx.x * blockDim.x + threadIdx.x;
    if (i < n1) g_len[i] = 0;
    if (i < G * 32) g_pool[i] = 0.f;
    if (i < G) g_cnt[i] = 0;
}

// ---------------- nodes-per-graph counts (batch sorted) ----------------
__global__ void k_cnt(const int* __restrict__ batch, int n) {
    int base = blockIdx.x * 256;
    int i = base + threadIdx.x;
    if (base >= n) return;
    int last = min(base + 255, n - 1);
    if (batch[base] == batch[last]) {
        if (threadIdx.x == 0) atomicAdd(&g_cnt[batch[base]], last - base + 1);
    } else if (i < n) {
        atomicAdd(&g_cnt[batch[i]], 1);
    }
}

// ---------------- in-degree count (int4 reads) ----------------
__global__ void k_count(const int* __restrict__ dst, int e) {
    int t = blockIdx.x * blockDim.x + threadIdx.x;
    int base = t * 4;
    if (base + 3 < e) {
        int4 d = *reinterpret_cast<const int4*>(dst + base);
        atomicAdd(&g_len[d.x], 1);
        atomicAdd(&g_len[d.y], 1);
        atomicAdd(&g_len[d.z], 1);
        atomicAdd(&g_len[d.w], 1);
    } else {
        for (int i = base; i < e; i++) atomicAdd(&g_len[dst[i]], 1);
    }
}
__global__ void k_dinv(int n) {
    int i = blockIdx.x * blockDim.x + threadIdx.x;
    if (i < n) g_dinv[i] = rsqrtf((float)(g_len[i] + 1));  // +1 self-loop
}

// ---------------- exclusive scan of g_len -> g_rowptr ----------------
__global__ void k_scan1(int n1) {
    __shared__ int sw[8];
    int gid = blockIdx.x * 256 + threadIdx.x;
    int lane = threadIdx.x & 31, wid = threadIdx.x >> 5;
    int v = (gid < n1) ? g_len[gid] : 0;
    int x = v;
    for (int o = 1; o < 32; o <<= 1) { int t = __shfl_up_sync(~0u, x, o); if (lane >= o) x += t; }
    if (lane == 31) sw[wid] = x;
    __syncthreads();
    if (wid == 0) {
        int y = (lane < 8) ? sw[lane] : 0;
        for (int o = 1; o < 8; o <<= 1) { int t = __shfl_up_sync(~0u, y, o); if (lane >= o) y += t; }
        if (lane < 8) sw[lane] = y;
    }
    __syncthreads();
    int off = wid ? sw[wid - 1] : 0;
    if (gid < n1) g_rowptr[gid] = x - v + off;
    if (threadIdx.x == 255) g_bsum[blockIdx.x] = off + x;
}
__global__ void k_scan2(int nb) {   // single block, 512 threads
    __shared__ int sw[16];
    int t = threadIdx.x, lane = t & 31, wid = t >> 5;
    int v = (t < nb) ? g_bsum[t] : 0;
    int x = v;
    for (int o = 1; o < 32; o <<= 1) { int q = __shfl_up_sync(~0u, x, o); if (lane >= o) x += q; }
    if (lane == 31) sw[wid] = x;
    __syncthreads();
    if (wid == 0) {
        int y = (lane < 16) ? sw[lane] : 0;
        for (int o = 1; o < 16; o <<= 1) { int q = __shfl_up_sync(~0u, y, o); if (lane >= o) y += q; }
        if (lane < 16) sw[lane] = y;
    }
    __syncthreads();
    int off = wid ? sw[wid - 1] : 0;
    if (t < nb) g_bsum[t] = x - v + off;   // exclusive
}
__global__ void k_scan3(int n1) {
    int gid = blockIdx.x * 256 + threadIdx.x;
    if (gid < n1) {
        int v = g_rowptr[gid] + g_bsum[blockIdx.x];
        g_rowptr[gid] = v;
        g_cur[gid] = v;   // absolute placement cursor
    }
}

// ---------------- place edges into CSR ----------------
__global__ void k_place(const int* __restrict__ src, const int* __restrict__ dst, int e) {
    int i = blockIdx.x * blockDim.x + threadIdx.x;
    if (i >= e) return;
    int s = src[i], d = dst[i];
    int pos = atomicAdd(&g_cur[d], 1);
    g_csr[pos] = make_int2(s, __float_as_int(g_dinv[s] * g_dinv[d]));
}

// ---------------- pad+convert x [N,25]f32 -> [N,32]f16 ----------------
__global__ void k_padh(const float* __restrict__ x, __half* __restrict__ P, int n) {
    int tid = blockIdx.x * blockDim.x + threadIdx.x;
    int i = tid >> 4, c = tid & 15;          // c = half2 column
    if (i >= n) return;
    int f0 = 2 * c, f1 = 2 * c + 1;
    float v0 = (f0 < IN_DIM) ? x[(size_t)i * IN_DIM + f0] : 0.f;
    float v1 = (f1 < IN_DIM) ? x[(size_t)i * IN_DIM + f1] : 0.f;
    reinterpret_cast<__half2*>(P)[(size_t)i * 16 + c] = __floats2half2_rn(v0, v1);
}

// ---------------- pull (half input): out[i] = sum_j w_ij*act(in[j]) + dinv_i^2*act(in[i]) ----
// F = feature count. in is __half [N,F]. Output fp32 (or fused pool for POOL=true).
template<int F, bool RELU, bool POOL>
__global__ void k_pull_h(const __half* __restrict__ in, float* __restrict__ out,
                         const float* __restrict__ b, const int* __restrict__ batch, int n) {
    constexpr int C = F / 2;                 // half2 columns per row
    int warp = (blockIdx.x * blockDim.x + threadIdx.x) >> 5;
    int lane = threadIdx.x & 31;
    if (warp >= n) return;
    const __half2* in2 = reinterpret_cast<const __half2*>(in);
    int beg = g_rowptr[warp], end = g_rowptr[warp + 1];
    float a0 = 0.f, a1 = 0.f;
    int col = (F == 64) ? lane : (lane & 15);
    int jbase = (F == 64) ? 0 : ((lane >> 4) * 16);
    constexpr int JL = (F == 64) ? 32 : 16;  // edges processed per staged chunk per (half-)warp

    int base = beg;
    for (; base + 32 <= end; base += 32) {
        int2 m = g_csr[base + lane];
#pragma unroll
        for (int j = 0; j < JL; j++) {
            int s = __shfl_sync(~0u, m.x, jbase + j);
            float w = __int_as_float(__shfl_sync(~0u, m.y, jbase + j));
            __half2 h = __ldg(&in2[(size_t)s * C + col]);
            float2 f = __half22float2(h);
            if (RELU) { f.x = fmaxf(f.x, 0.f); f.y = fmaxf(f.y, 0.f); }
            a0 = fmaf(w, f.x, a0);
            a1 = fmaf(w, f.y, a1);
        }
    }
    int rem = end - base;
    if (rem > 0) {
        int2 m = (lane < rem) ? g_csr[base + lane] : make_int2(0, 0);
        for (int j = 0; j < JL; j++) {
            int idx = jbase + j;
            int s = __shfl_sync(~0u, m.x, idx);
            float w = __int_as_float(__shfl_sync(~0u, m.y, idx));
            if (idx < rem) {
                __half2 h = __ldg(&in2[(size_t)s * C + col]);
                float2 f = __half22float2(h);
                if (RELU) { f.x = fmaxf(f.x, 0.f); f.y = fmaxf(f.y, 0.f); }
                a0 = fmaf(w, f.x, a0);
                a1 = fmaf(w, f.y, a1);
            }
        }
    }
    if (F == 32) {  // combine the two half-warps' partial sums
        a0 += __shfl_xor_sync(~0u, a0, 16);
        a1 += __shfl_xor_sync(~0u, a1, 16);
    }
    // self-loop term
    float di = g_dinv[warp], ws = di * di;
    {
        __half2 h = in2[(size_t)warp * C + col];
        float2 f = __half22float2(h);
        if (RELU) { f.x = fmaxf(f.x, 0.f); f.y = fmaxf(f.y, 0.f); }
        a0 = fmaf(ws, f.x, a0);
        a1 = fmaf(ws, f.y, a1);
    }
    if (POOL) {
        // out3 = agg + b3; pool += relu(out3)
        if (lane < 16) {
            float p0 = fmaxf(a0 + b[2 * col], 0.f);
            float p1 = fmaxf(a1 + b[2 * col + 1], 0.f);
            int g = batch[warp];
            atomicAdd(&g_pool[g * 32 + 2 * col], p0);
            atomicAdd(&g_pool[g * 32 + 2 * col + 1], p1);
        }
    } else if (F == 64) {
        reinterpret_cast<float2*>(out)[(size_t)warp * C + col] = make_float2(a0, a1);
    } else {
        if (lane < 16)
            reinterpret_cast<float2*>(out)[(size_t)warp * C + col] = make_float2(a0, a1);
    }
}

// ---------------- dense: O = act(X) @ W (+b), fp32 or fp16 output ----------------
template<int K, int F, bool RELU, bool BIAS, bool OHALF>
__global__ void k_gemm(const float* __restrict__ X, const float* __restrict__ W,
                       const float* __restrict__ b, void* __restrict__ Oout,
                       int n, int kreal) {
    constexpr int NPB = 256 / F;
    __shared__ float Wsh[K * F];
    __shared__ float Xsh[NPB * K];
    __shared__ float bsh[F];
    int base = blockIdx.x * NPB;
    for (int idx = threadIdx.x; idx < K * F; idx += 256) {
        int k = idx / F;
        Wsh[idx] = (k < kreal) ? W[idx] : 0.f;
    }
    if (BIAS && threadIdx.x < F) bsh[threadIdx.x] = b[threadIdx.x];
    for (int idx = threadIdx.x; idx < NPB * K; idx += 256) {
        int node = base + idx / K;
        int k = idx % K;
        float v = (node < n) ? X[(size_t)node * K + k] : 0.f;
        if (RELU) v = fmaxf(v, 0.f);
        Xsh[idx] = v;
    }
    __syncthreads();
    int il = threadIdx.x / F, f = threadIdx.x % F;
    int node = base + il;
    if (node >= n) return;
    float acc = 0.f;
#pragma unroll
    for (int k = 0; k < K; k++)
        acc = fmaf(Xsh[il * K + k], Wsh[k * F + f], acc);
    float v = BIAS ? (acc + bsh[f]) : acc;
    if (OHALF) ((__half*)Oout)[(size_t)node * F + f] = __float2half_rn(v);
    else       ((float*)Oout)[(size_t)node * F + f] = v;
}

// ---------------- MLP head ----------------
__global__ void k_head(const float* __restrict__ Wh1, const float* __restrict__ bh1,
                       const float* __restrict__ Wh2, const float* __restrict__ bh2,
                       float* __restrict__ y, int G) {
    __shared__ float W1s[32 * 32], b1s[32], W2s[32];
    int t = threadIdx.x;
    for (int idx = t; idx < 1024; idx += blockDim.x) W1s[idx] = Wh1[idx];
    if (t < 32) { b1s[t] = bh1[t]; W2s[t] = Wh2[t]; }
    __syncthreads();
    if (t >= G) return;
    float inv = 1.f / fmaxf((float)g_cnt[t], 1.f);
    float row[32];
#pragma unroll
    for (int k = 0; k < 32; k++) row[k] = g_pool[t * 32 + k] * inv;
    float acc = bh2[0];
#pragma unroll
    for (int j = 0; j < 32; j++) {
        float s = b1s[j];
#pragma unroll
        for (int k = 0; k < 32; k++) s = fmaf(row[k], W1s[k * 32 + j], s);
        acc = fmaf(fmaxf(s, 0.f), W2s[j], acc);
    }
    y[t] = acc;
}

extern "C" void kernel_launch(void* const* d_in, const int* in_sizes, int n_in,
                              void* d_out, int out_size) {
    const float* x   = (const float*)d_in[0];
    const int*   ei  = (const int*)d_in[1];
    const int*   bat = (const int*)d_in[2];
    const float* W1  = (const float*)d_in[3];
    const float* b1  = (const float*)d_in[4];
    const float* W2  = (const float*)d_in[5];
    const float* b2  = (const float*)d_in[6];
    const float* W3  = (const float*)d_in[7];
    const float* b3  = (const float*)d_in[8];
    const float* Wh1 = (const float*)d_in[9];
    const float* bh1 = (const float*)d_in[10];
    const float* Wh2 = (const float*)d_in[11];
    const float* bh2 = (const float*)d_in[12];
    float* y = (float*)d_out;

    int n = in_sizes[0] / IN_DIM;
    int e = in_sizes[1] / 2;
    int G = out_size;
    int n1 = n + 1;
    const int* src = ei;
    const int* dst = ei + e;

    float *A, *C;
    __half* H;
    cudaGetSymbolAddress((void**)&A, g_bufA);
    cudaGetSymbolAddress((void**)&C, g_bufC);
    cudaGetSymbolAddress((void**)&H, g_hbuf);

    const int T = 256;
    auto blk = [](long long w, int t) { return (int)((w + t - 1) / t); };
    int scan_blocks = blk(n1, 256);

    // ---- CSR build (counting sort by dst) + zeroing ----
    k_init <<<blk(n1, T), T>>>(n1, G);
    k_cnt  <<<blk(n, T), T>>>(bat, n);
    k_count<<<blk((e + 3) / 4, T), T>>>(dst, e);
    k_dinv <<<blk(n, T), T>>>(n);
    k_scan1<<<scan_blocks, 256>>>(n1);
    k_scan2<<<1, 512>>>(scan_blocks);
    k_scan3<<<scan_blocks, 256>>>(n1);
    k_place<<<blk(e, T), T>>>(src, dst, e);

    // ---- layer pipeline: A@(XW) == (A@X)W, pull inputs in fp16 ----
    // xh = half(pad(x)) -> H[N,32]
    k_padh<<<blk((long long)n * 16, T), T>>>(x, H, n);
    // agg1 = pull(xh) -> C[N,32] fp32
    k_pull_h<32, false, false><<<blk((long long)n * 32, T), T>>>(H, C, nullptr, nullptr, n);
    // h1 = agg1@W1 + b1 -> H[N,64] fp16
    k_gemm<32, 64, false, true, true><<<blk(n, 4), 256>>>(C, W1, b1, H, n, IN_DIM);
    // agg2 = pull(relu(h1)) -> C[N,64] fp32
    k_pull_h<64, true, false><<<blk((long long)n * 32, T), T>>>(H, C, nullptr, nullptr, n);
    // h2 = agg2@W2 + b2 -> A[N,64] fp32
    k_gemm<64, 64, false, true, false><<<blk(n, 4), 256>>>(C, W2, b2, A, n, 64);
    // T = relu(h2)@W3 -> H[N,32] fp16
    k_gemm<64, 32, true, false, true><<<blk(n, 8), 256>>>(A, W3, nullptr, H, n, 64);
    // out3 = pull(T) + b3; pool += relu(out3)   (fused)
    k_pull_h<32, false, true><<<blk((long long)n * 32, T), T>>>(H, nullptr, b3, bat, n);

    // ---- head ----
    k_head<<<1, 256>>>(Wh1, bh1, Wh2, bh2, y, G);
}

// round 6
// speedup vs baseline: 1.1182x; 1.1182x over previous
#include <cuda_runtime.h>

#define NMAX 100000
#define EMAX 3200000
#define GMAXG 256
#define IN_DIM 25

// Scratch
__device__ float g_bufA[NMAX * 64];
__device__ float g_bufB[NMAX * 64];
__device__ float g_bufC[NMAX * 64];
__device__ int   g_csr[EMAX];        // src indices grouped by dst (weights factored out!)
__device__ int   g_rowptr[NMAX + 2];
__device__ int   g_len[NMAX + 1];
__device__ int   g_cur[NMAX + 1];
__device__ int   g_bsum[512];
__device__ float g_pool[GMAXG * 32];
__device__ int   g_cnt[GMAXG];

// ---------------- init: zero len + pool + cnt ----------------
__global__ void k_init(int n1, int G) {
    int i = blockIdx.x * blockDim.x + threadIdx.x;
    if (i < n1) g_len[i] = 0;
    if (i < G * 32) g_pool[i] = 0.f;
    if (i < G) g_cnt[i] = 0;
}

// ---------------- nodes-per-graph counts (batch sorted) ----------------
__global__ void k_cnt(const int* __restrict__ batch, int n) {
    int base = blockIdx.x * 256;
    int i = base + threadIdx.x;
    if (base >= n) return;
    int last = min(base + 255, n - 1);
    if (batch[base] == batch[last]) {
        if (threadIdx.x == 0) atomicAdd(&g_cnt[batch[base]], last - base + 1);
    } else if (i < n) {
        atomicAdd(&g_cnt[batch[i]], 1);
    }
}

// ---------------- in-degree count (int4 reads) ----------------
__global__ void k_count(const int* __restrict__ dst, int e) {
    int t = blockIdx.x * blockDim.x + threadIdx.x;
    int base = t * 4;
    if (base + 3 < e) {
        int4 d = *reinterpret_cast<const int4*>(dst + base);
        atomicAdd(&g_len[d.x], 1);
        atomicAdd(&g_len[d.y], 1);
        atomicAdd(&g_len[d.z], 1);
        atomicAdd(&g_len[d.w], 1);
    } else {
        for (int i = base; i < e; i++) atomicAdd(&g_len[dst[i]], 1);
    }
}

// ---------------- exclusive scan of g_len -> g_rowptr ----------------
__global__ void k_scan1(int n1) {
    __shared__ int sw[8];
    int gid = blockIdx.x * 256 + threadIdx.x;
    int lane = threadIdx.x & 31, wid = threadIdx.x >> 5;
    int v = (gid < n1) ? g_len[gid] : 0;
    int x = v;
    for (int o = 1; o < 32; o <<= 1) { int t = __shfl_up_sync(~0u, x, o); if (lane >= o) x += t; }
    if (lane == 31) sw[wid] = x;
    __syncthreads();
    if (wid == 0) {
        int y = (lane < 8) ? sw[lane] : 0;
        for (int o = 1; o < 8; o <<= 1) { int t = __shfl_up_sync(~0u, y, o); if (lane >= o) y += t; }
        if (lane < 8) sw[lane] = y;
    }
    __syncthreads();
    int off = wid ? sw[wid - 1] : 0;
    if (gid < n1) g_rowptr[gid] = x - v + off;
    if (threadIdx.x == 255) g_bsum[blockIdx.x] = off + x;
}
__global__ void k_scan2(int nb) {   // single block, 512 threads
    __shared__ int sw[16];
    int t = threadIdx.x, lane = t & 31, wid = t >> 5;
    int v = (t < nb) ? g_bsum[t] : 0;
    int x = v;
    for (int o = 1; o < 32; o <<= 1) { int q = __shfl_up_sync(~0u, x, o); if (lane >= o) x += q; }
    if (lane == 31) sw[wid] = x;
    __syncthreads();
    if (wid == 0) {
        int y = (lane < 16) ? sw[lane] : 0;
        for (int o = 1; o < 16; o <<= 1) { int q = __shfl_up_sync(~0u, y, o); if (lane >= o) y += q; }
        if (lane < 16) sw[lane] = y;
    }
    __syncthreads();
    int off = wid ? sw[wid - 1] : 0;
    if (t < nb) g_bsum[t] = x - v + off;   // exclusive
}
__global__ void k_scan3(int n1) {
    int gid = blockIdx.x * 256 + threadIdx.x;
    if (gid < n1) {
        int v = g_rowptr[gid] + g_bsum[blockIdx.x];
        g_rowptr[gid] = v;
        g_cur[gid] = v;   // absolute placement cursor
    }
}

// ---------------- place edges into CSR (src only — no weights) ----------------
__global__ void k_place(const int* __restrict__ src, const int* __restrict__ dst, int e) {
    int i = blockIdx.x * blockDim.x + threadIdx.x;
    if (i >= e) return;
    int d = dst[i];
    int pos = atomicAdd(&g_cur[d], 1);
    g_csr[pos] = src[i];
}

// ---------------- pad+pre-scale x: P[i,f] = dinv[i] * x[i,f], [N,32] ----------------
__global__ void k_pad(const float* __restrict__ x, float* __restrict__ P, int n) {
    int tid = blockIdx.x * blockDim.x + threadIdx.x;
    int i = tid >> 5, f = tid & 31;
    if (i >= n) return;
    float di = rsqrtf((float)(g_len[i] + 1));
    P[(size_t)i * 32 + f] = (f < IN_DIM) ? x[(size_t)i * IN_DIM + f] * di : 0.f;
}

// ---------------- pull: out[i] = dinv_i * (sum_{j in N(i)} in[j] + in[i])  (+b3/pool) ----
// in is pre-scaled by dinv (s = dinv .* act(h)), so no per-edge weights.
template<int F, bool POOL>
__global__ void k_pull(const float* __restrict__ in, float* __restrict__ out,
                       const float* __restrict__ b, const int* __restrict__ batch, int n) {
    constexpr int C2 = F / 2;                   // float2 columns per row
    int warp = (blockIdx.x * blockDim.x + threadIdx.x) >> 5;
    int lane = threadIdx.x & 31;
    if (warp >= n) return;
    const float2* in2 = reinterpret_cast<const float2*>(in);
    int beg = g_rowptr[warp], end = g_rowptr[warp + 1];
    float dinv = rsqrtf((float)(end - beg + 1));
    float a0 = 0.f, a1 = 0.f;
    int col = (F == 64) ? lane : (lane & 15);
    int jbase = (F == 64) ? 0 : ((lane >> 4) * 16);
    constexpr int JL = (F == 64) ? 32 : 16;

    int base = beg;
    for (; base + 32 <= end; base += 32) {
        int m = g_csr[base + lane];
#pragma unroll
        for (int j = 0; j < JL; j++) {
            int s = __shfl_sync(~0u, m, jbase + j);
            float2 f = __ldg(&in2[(size_t)s * C2 + col]);
            a0 += f.x;
            a1 += f.y;
        }
    }
    int rem = end - base;
    if (rem > 0) {
        int m = (lane < rem) ? g_csr[base + lane] : 0;
        for (int j = 0; j < JL; j++) {
            int idx = jbase + j;
            int s = __shfl_sync(~0u, m, idx);
            if (idx < rem) {
                float2 f = __ldg(&in2[(size_t)s * C2 + col]);
                a0 += f.x;
                a1 += f.y;
            }
        }
    }
    if (F == 32) {   // combine the two half-warps' edge partial sums
        a0 += __shfl_xor_sync(~0u, a0, 16);
        a1 += __shfl_xor_sync(~0u, a1, 16);
    }
    // self-loop term (in[] is pre-scaled: s_i = dinv_i * h_i)
    {
        float2 f = in2[(size_t)warp * C2 + col];
        a0 += f.x;
        a1 += f.y;
    }
    a0 *= dinv;
    a1 *= dinv;
    if (POOL) {
        if (lane < 16) {
            float p0 = fmaxf(a0 + b[2 * col], 0.f);
            float p1 = fmaxf(a1 + b[2 * col + 1], 0.f);
            int g = batch[warp];
            atomicAdd(&g_pool[g * 32 + 2 * col], p0);
            atomicAdd(&g_pool[g * 32 + 2 * col + 1], p1);
        }
    } else if (F == 64) {
        reinterpret_cast<float2*>(out)[(size_t)warp * C2 + col] = make_float2(a0, a1);
    } else {
        if (lane < 16)
            reinterpret_cast<float2*>(out)[(size_t)warp * C2 + col] = make_float2(a0, a1);
    }
}

// ---------------- dense: O = X @ W, epilogue: (+b) (relu) (dinv scale) ----------------
template<int K, int F, bool BIAS, bool RELU_OUT, bool SCALE>
__global__ void k_gemm(const float* __restrict__ X, const float* __restrict__ W,
                       const float* __restrict__ b, float* __restrict__ O,
                       int n, int kreal) {
    constexpr int NPB = 256 / F;
    __shared__ float Wsh[K * F];
    __shared__ float Xsh[NPB * K];
    __shared__ float bsh[F];
    int base = blockIdx.x * NPB;
    for (int idx = threadIdx.x; idx < K * F; idx += 256) {
        int k = idx / F;
        Wsh[idx] = (k < kreal) ? W[idx] : 0.f;
    }
    if (BIAS && threadIdx.x < F) bsh[threadIdx.x] = b[threadIdx.x];
    for (int idx = threadIdx.x; idx < NPB * K; idx += 256) {
        int node = base + idx / K;
        int k = idx % K;
        Xsh[idx] = (node < n) ? X[(size_t)node * K + k] : 0.f;
    }
    __syncthreads();
    int il = threadIdx.x / F, f = threadIdx.x % F;
    int node = base + il;
    if (node >= n) return;
    float acc = 0.f;
#pragma unroll
    for (int k = 0; k < K; k++)
        acc = fmaf(Xsh[il * K + k], Wsh[k * F + f], acc);
    if (BIAS) acc += bsh[f];
    if (RELU_OUT) acc = fmaxf(acc, 0.f);
    if (SCALE) acc *= rsqrtf((float)(g_len[node] + 1));
    O[(size_t)node * F + f] = acc;
}

// ---------------- MLP head ----------------
__global__ void k_head(const float* __restrict__ Wh1, const float* __restrict__ bh1,
                       const float* __restrict__ Wh2, const float* __restrict__ bh2,
                       float* __restrict__ y, int G) {
    __shared__ float W1s[32 * 32], b1s[32], W2s[32];
    int t = threadIdx.x;
    for (int idx = t; idx < 1024; idx += blockDim.x) W1s[idx] = Wh1[idx];
    if (t < 32) { b1s[t] = bh1[t]; W2s[t] = Wh2[t]; }
    __syncthreads();
    if (t >= G) return;
    float inv = 1.f / fmaxf((float)g_cnt[t], 1.f);
    float row[32];
#pragma unroll
    for (int k = 0; k < 32; k++) row[k] = g_pool[t * 32 + k] * inv;
    float acc = bh2[0];
#pragma unroll
    for (int j = 0; j < 32; j++) {
        float s = b1s[j];
#pragma unroll
        for (int k = 0; k < 32; k++) s = fmaf(row[k], W1s[k * 32 + j], s);
        acc = fmaf(fmaxf(s, 0.f), W2s[j], acc);
    }
    y[t] = acc;
}

extern "C" void kernel_launch(void* const* d_in, const int* in_sizes, int n_in,
                              void* d_out, int out_size) {
    const float* x   = (const float*)d_in[0];
    const int*   ei  = (const int*)d_in[1];
    const int*   bat = (const int*)d_in[2];
    const float* W1  = (const float*)d_in[3];
    const float* b1  = (const float*)d_in[4];
    const float* W2  = (const float*)d_in[5];
    const float* b2  = (const float*)d_in[6];
    const float* W3  = (const float*)d_in[7];
    const float* b3  = (const float*)d_in[8];
    const float* Wh1 = (const float*)d_in[9];
    const float* bh1 = (const float*)d_in[10];
    const float* Wh2 = (const float*)d_in[11];
    const float* bh2 = (const float*)d_in[12];
    float* y = (float*)d_out;

    int n = in_sizes[0] / IN_DIM;
    int e = in_sizes[1] / 2;
    int G = out_size;
    int n1 = n + 1;
    const int* src = ei;
    const int* dst = ei + e;

    float *A, *B, *C;
    cudaGetSymbolAddress((void**)&A, g_bufA);
    cudaGetSymbolAddress((void**)&B, g_bufB);
    cudaGetSymbolAddress((void**)&C, g_bufC);

    const int T = 256;
    auto blk = [](long long w, int t) { return (int)((w + t - 1) / t); };
    int scan_blocks = blk(n1, 256);

    // ---- CSR build (counting sort by dst, src-only payload) ----
    k_init <<<blk(n1, T), T>>>(n1, G);
    k_cnt  <<<blk(n, T), T>>>(bat, n);
    k_count<<<blk((e + 3) / 4, T), T>>>(dst, e);
    k_scan1<<<scan_blocks, 256>>>(n1);
    k_scan2<<<1, 512>>>(scan_blocks);
    k_scan3<<<scan_blocks, 256>>>(n1);
    k_place<<<blk(e, T), T>>>(src, dst, e);

    // ---- layer pipeline, activations pre-scaled by dinv ----
    // P = dinv .* pad(x) -> A[N,32]
    k_pad<<<blk((long long)n * 32, T), T>>>(x, A, n);
    // agg1 = dinv.*(gather-sum P + P) -> C[N,32]
    k_pull<32, false><<<blk((long long)n * 32, T), T>>>(A, C, nullptr, nullptr, n);
    // s1 = dinv .* relu(agg1@W1 + b1) -> B[N,64]
    k_gemm<32, 64, true, true, true><<<blk(n, 4), 256>>>(C, W1, b1, B, n, IN_DIM);
    // agg2 = dinv.*(gather-sum s1 + s1) -> A[N,64]
    k_pull<64, false><<<blk((long long)n * 32, T), T>>>(B, A, nullptr, nullptr, n);
    // r2 = relu(agg2@W2 + b2) -> C[N,64]
    k_gemm<64, 64, true, true, false><<<blk(n, 4), 256>>>(A, W2, b2, C, n, 64);
    // s2 = dinv .* (r2@W3) -> B[N,32]
    k_gemm<64, 32, false, false, true><<<blk(n, 8), 256>>>(C, W3, nullptr, B, n, 64);
    // out3 = dinv.*(gather-sum s2 + s2) + b3 ; pool += relu(out3)   (fused)
    k_pull<32, true><<<blk((long long)n * 32, T), T>>>(B, nullptr, b3, bat, n);

    // ---- head ----
    k_head<<<1, 256>>>(Wh1, bh1, Wh2, bh2, y, G);
}

// round 8
// speedup vs baseline: 1.2385x; 1.1075x over previous
#include <cuda_runtime.h>

#define NMAX 100000
#define EMAX 3200000
#define GMAXG 256
#define IN_DIM 25

// Scratch
__device__ float g_bufA[NMAX * 64];
__device__ float g_bufB[NMAX * 64];
__device__ float g_bufC[NMAX * 64];
__device__ int   g_csr[EMAX];        // src indices grouped by dst (weights factored out)
__device__ int   g_rowptr[NMAX + 2];
__device__ int   g_len[NMAX + 1];
__device__ int   g_cur[NMAX + 1];
__device__ int   g_bsum[512];
__device__ float g_pool[GMAXG * 32];
__device__ int   g_cnt[GMAXG];

// ---------------- init: zero len + pool + cnt ----------------
__global__ void k_init(int n1, int G) {
    int i = blockIdx.x * blockDim.x + threadIdx.x;
    if (i < n1) g_len[i] = 0;
    if (i < G * 32) g_pool[i] = 0.f;
    if (i < G) g_cnt[i] = 0;
}

// ---------------- nodes-per-graph counts (batch sorted) ----------------
__global__ void k_cnt(const int* __restrict__ batch, int n) {
    int base = blockIdx.x * 256;
    int i = base + threadIdx.x;
    if (base >= n) return;
    int last = min(base + 255, n - 1);
    if (batch[base] == batch[last]) {
        if (threadIdx.x == 0) atomicAdd(&g_cnt[batch[base]], last - base + 1);
    } else if (i < n) {
        atomicAdd(&g_cnt[batch[i]], 1);
    }
}

// ---------------- in-degree count (int4 reads) ----------------
__global__ void k_count(const int* __restrict__ dst, int e) {
    int t = blockIdx.x * blockDim.x + threadIdx.x;
    int base = t * 4;
    if (base + 3 < e) {
        int4 d = *reinterpret_cast<const int4*>(dst + base);
        atomicAdd(&g_len[d.x], 1);
        atomicAdd(&g_len[d.y], 1);
        atomicAdd(&g_len[d.z], 1);
        atomicAdd(&g_len[d.w], 1);
    } else {
        for (int i = base; i < e; i++) atomicAdd(&g_len[dst[i]], 1);
    }
}

// ---------------- exclusive scan of g_len -> g_rowptr ----------------
__global__ void k_scan1(int n1) {
    __shared__ int sw[8];
    int gid = blockIdx.x * 256 + threadIdx.x;
    int lane = threadIdx.x & 31, wid = threadIdx.x >> 5;
    int v = (gid < n1) ? g_len[gid] : 0;
    int x = v;
    for (int o = 1; o < 32; o <<= 1) { int t = __shfl_up_sync(~0u, x, o); if (lane >= o) x += t; }
    if (lane == 31) sw[wid] = x;
    __syncthreads();
    if (wid == 0) {
        int y = (lane < 8) ? sw[lane] : 0;
        for (int o = 1; o < 8; o <<= 1) { int t = __shfl_up_sync(~0u, y, o); if (lane >= o) y += t; }
        if (lane < 8) sw[lane] = y;
    }
    __syncthreads();
    int off = wid ? sw[wid - 1] : 0;
    if (gid < n1) g_rowptr[gid] = x - v + off;
    if (threadIdx.x == 255) g_bsum[blockIdx.x] = off + x;
}
__global__ void k_scan2(int nb) {   // single block, 512 threads
    __shared__ int sw[16];
    int t = threadIdx.x, lane = t & 31, wid = t >> 5;
    int v = (t < nb) ? g_bsum[t] : 0;
    int x = v;
    for (int o = 1; o < 32; o <<= 1) { int q = __shfl_up_sync(~0u, x, o); if (lane >= o) x += q; }
    if (lane == 31) sw[wid] = x;
    __syncthreads();
    if (wid == 0) {
        int y = (lane < 16) ? sw[lane] : 0;
        for (int o = 1; o < 16; o <<= 1) { int q = __shfl_up_sync(~0u, y, o); if (lane >= o) y += q; }
        if (lane < 16) sw[lane] = y;
    }
    __syncthreads();
    int off = wid ? sw[wid - 1] : 0;
    if (t < nb) g_bsum[t] = x - v + off;   // exclusive
}
__global__ void k_scan3(int n1) {
    int gid = blockIdx.x * 256 + threadIdx.x;
    if (gid < n1) {
        int v = g_rowptr[gid] + g_bsum[blockIdx.x];
        g_rowptr[gid] = v;
        g_cur[gid] = v;   // absolute placement cursor
    }
}

// ---------------- place edges into CSR (src only) ----------------
__global__ void k_place(const int* __restrict__ src, const int* __restrict__ dst, int e) {
    int i = blockIdx.x * blockDim.x + threadIdx.x;
    if (i >= e) return;
    int d = dst[i];
    int pos = atomicAdd(&g_cur[d], 1);
    g_csr[pos] = src[i];
}

// ---------------- pad+pre-scale x: P[i,f] = dinv[i] * x[i,f], [N,32] ----------------
__global__ void k_pad(const float* __restrict__ x, float* __restrict__ P, int n) {
    int tid = blockIdx.x * blockDim.x + threadIdx.x;
    int i = tid >> 5, f = tid & 31;
    if (i >= n) return;
    float di = rsqrtf((float)(g_len[i] + 1));
    P[(size_t)i * 32 + f] = (f < IN_DIM) ? x[(size_t)i * IN_DIM + f] * di : 0.f;
}

// ---------------- pull: out[i] = dinv_i * (sum_{j in N(i)} in[j] + in[i])  (+b3/pool) ----
// in[] is pre-scaled by dinv at the producer. Scalar per-lane loads: each warp
// load covers exactly one 128B line (1 L1TEX wavefront per LDG).
template<int F, bool POOL>
__global__ void k_pull(const float* __restrict__ in, float* __restrict__ out,
                       const float* __restrict__ b, const int* __restrict__ batch, int n) {
    int warp = (blockIdx.x * blockDim.x + threadIdx.x) >> 5;
    int lane = threadIdx.x & 31;
    if (warp >= n) return;
    int beg = g_rowptr[warp], end = g_rowptr[warp + 1];
    float dinv = rsqrtf((float)(end - beg + 1));
    float a0 = 0.f, a1 = 0.f;

    int base = beg;
    for (; base + 32 <= end; base += 32) {
        int m = g_csr[base + lane];
#pragma unroll
        for (int j = 0; j < 32; j++) {
            int s = __shfl_sync(~0u, m, j);
            a0 += __ldg(&in[(size_t)s * F + lane]);
            if (F == 64) a1 += __ldg(&in[(size_t)s * F + 32 + lane]);
        }
    }
    int rem = end - base;
    if (rem > 0) {
        int m = (lane < rem) ? g_csr[base + lane] : 0;
        for (int j = 0; j < rem; j++) {
            int s = __shfl_sync(~0u, m, j);
            a0 += __ldg(&in[(size_t)s * F + lane]);
            if (F == 64) a1 += __ldg(&in[(size_t)s * F + 32 + lane]);
        }
    }
    // self-loop (in[] pre-scaled: s_i = dinv_i * h_i)
    a0 += in[(size_t)warp * F + lane];
    if (F == 64) a1 += in[(size_t)warp * F + 32 + lane];
    a0 *= dinv;
    if (F == 64) a1 *= dinv;

    if (POOL) {
        float p0 = fmaxf(a0 + b[lane], 0.f);
        atomicAdd(&g_pool[batch[warp] * 32 + lane], p0);
    } else {
        out[(size_t)warp * F + lane] = a0;
        if (F == 64) out[(size_t)warp * F + 32 + lane] = a1;
    }
}

// ---------------- dense: O = X @ W, epilogue: (+b) (relu) (dinv scale) ----------------
template<int K, int F, bool BIAS, bool RELU_OUT, bool SCALE>
__global__ void k_gemm(const float* __restrict__ X, const float* __restrict__ W,
                       const float* __restrict__ b, float* __restrict__ O,
                       int n, int kreal) {
    constexpr int NPB = 256 / F;
    __shared__ float Wsh[K * F];
    __shared__ float Xsh[NPB * K];
    __shared__ float bsh[F];
    int base = blockIdx.x * NPB;
    for (int idx = threadIdx.x; idx < K * F; idx += 256) {
        int k = idx / F;
        Wsh[idx] = (k < kreal) ? W[idx] : 0.f;
    }
    if (BIAS && threadIdx.x < F) bsh[threadIdx.x] = b[threadIdx.x];
    for (int idx = threadIdx.x; idx < NPB * K; idx += 256) {
        int node = base + idx / K;
        int k = idx % K;
        Xsh[idx] = (node < n) ? X[(size_t)node * K + k] : 0.f;
    }
    __syncthreads();
    int il = threadIdx.x / F, f = threadIdx.x % F;
    int node = base + il;
    if (node >= n) return;
    float acc = 0.f;
#pragma unroll
    for (int k = 0; k < K; k++)
        acc = fmaf(Xsh[il * K + k], Wsh[k * F + f], acc);
    if (BIAS) acc += bsh[f];
    if (RELU_OUT) acc = fmaxf(acc, 0.f);
    if (SCALE) acc *= rsqrtf((float)(g_len[node] + 1));
    O[(size_t)node * F + f] = acc;
}

// ---------------- MLP head ----------------
__global__ void k_head(const float* __restrict__ Wh1, const float* __restrict__ bh1,
                       const float* __restrict__ Wh2, const float* __restrict__ bh2,
                       float* __restrict__ y, int G) {
    __shared__ float W1s[32 * 32], b1s[32], W2s[32];
    int t = threadIdx.x;
    for (int idx = t; idx < 1024; idx += blockDim.x) W1s[idx] = Wh1[idx];
    if (t < 32) { b1s[t] = bh1[t]; W2s[t] = Wh2[t]; }
    __syncthreads();
    if (t >= G) return;
    float inv = 1.f / fmaxf((float)g_cnt[t], 1.f);
    float row[32];
#pragma unroll
    for (int k = 0; k < 32; k++) row[k] = g_pool[t * 32 + k] * inv;
    float acc = bh2[0];
#pragma unroll
    for (int j = 0; j < 32; j++) {
        float s = b1s[j];
#pragma unroll
        for (int k = 0; k < 32; k++) s = fmaf(row[k], W1s[k * 32 + j], s);
        acc = fmaf(fmaxf(s, 0.f), W2s[j], acc);
    }
    y[t] = acc;
}

extern "C" void kernel_launch(void* const* d_in, const int* in_sizes, int n_in,
                              void* d_out, int out_size) {
    const float* x   = (const float*)d_in[0];
    const int*   ei  = (const int*)d_in[1];
    const int*   bat = (const int*)d_in[2];
    const float* W1  = (const float*)d_in[3];
    const float* b1  = (const float*)d_in[4];
    const float* W2  = (const float*)d_in[5];
    const float* b2  = (const float*)d_in[6];
    const float* W3  = (const float*)d_in[7];
    const float* b3  = (const float*)d_in[8];
    const float* Wh1 = (const float*)d_in[9];
    const float* bh1 = (const float*)d_in[10];
    const float* Wh2 = (const float*)d_in[11];
    const float* bh2 = (const float*)d_in[12];
    float* y = (float*)d_out;

    int n = in_sizes[0] / IN_DIM;
    int e = in_sizes[1] / 2;
    int G = out_size;
    int n1 = n + 1;
    const int* src = ei;
    const int* dst = ei + e;

    float *A, *B, *C;
    cudaGetSymbolAddress((void**)&A, g_bufA);
    cudaGetSymbolAddress((void**)&B, g_bufB);
    cudaGetSymbolAddress((void**)&C, g_bufC);

    const int T = 256;
    auto blk = [](long long w, int t) { return (int)((w + t - 1) / t); };
    int scan_blocks = blk(n1, 256);

    // ---- CSR build (counting sort by dst, src-only payload) ----
    k_init <<<blk(n1, T), T>>>(n1, G);
    k_cnt  <<<blk(n, T), T>>>(bat, n);
    k_count<<<blk((e + 3) / 4, T), T>>>(dst, e);
    k_scan1<<<scan_blocks, 256>>>(n1);
    k_scan2<<<1, 512>>>(scan_blocks);
    k_scan3<<<scan_blocks, 256>>>(n1);
    k_place<<<blk(e, T), T>>>(src, dst, e);

    // ---- layer pipeline, activations pre-scaled by dinv ----
    // P = dinv .* pad(x) -> A[N,32]
    k_pad<<<blk((long long)n * 32, T), T>>>(x, A, n);
    // agg1 = dinv.*(gather-sum P + P) -> C[N,32]
    k_pull<32, false><<<blk((long long)n * 32, T), T>>>(A, C, nullptr, nullptr, n);
    // s1 = dinv .* relu(agg1@W1 + b1) -> B[N,64]
    k_gemm<32, 64, true, true, true><<<blk(n, 4), 256>>>(C, W1, b1, B, n, IN_DIM);
    // agg2 = dinv.*(gather-sum s1 + s1) -> A[N,64]
    k_pull<64, false><<<blk((long long)n * 32, T), T>>>(B, A, nullptr, nullptr, n);
    // r2 = relu(agg2@W2 + b2) -> C[N,64]
    k_gemm<64, 64, true, true, false><<<blk(n, 4), 256>>>(A, W2, b2, C, n, 64);
    // s2 = dinv .* (r2@W3) -> B[N,32]
    k_gemm<64, 32, false, false, true><<<blk(n, 8), 256>>>(C, W3, nullptr, B, n, 64);
    // out3 = dinv.*(gather-sum s2 + s2) + b3 ; pool += relu(out3)   (fused)
    k_pull<32, true><<<blk((long long)n * 32, T), T>>>(B, nullptr, b3, bat, n);

    // ---- head ----
    k_head<<<1, 256>>>(Wh1, bh1, Wh2, bh2, y, G);
}

// round 12
// speedup vs baseline: 1.4081x; 1.1369x over previous
#include <cuda_runtime.h>
#include <cuda_fp16.h>

#define NMAX 100000
#define EMAX 3200000
#define GMAXG 256
#define IN_DIM 25

// Scratch
__device__ float  g_bufA[NMAX * 64];
__device__ float  g_bufB[NMAX * 64];
__device__ float  g_bufC[NMAX * 64];
__device__ __half g_hbuf[NMAX * 64];
__device__ int    g_csr[EMAX];        // src indices grouped by dst (weights factored out)
__device__ int    g_rowptr[NMAX + 2];
__device__ int    g_len[NMAX + 1];
__device__ int    g_cur[NMAX + 1];
__device__ int    g_bsum[512];
__device__ float  g_pool[GMAXG * 32];
__device__ int    g_cnt[GMAXG];

// ---------------- init: zero len + pool + cnt ----------------
__global__ void k_init(int n1, int G) {
    int i = blockIdx.x * blockDim.x + threadIdx.x;
    if (i < n1) g_len[i] = 0;
    if (i < G * 32) g_pool[i] = 0.f;
    if (i < G) g_cnt[i] = 0;
}

// ---------------- nodes-per-graph counts (batch sorted) ----------------
__global__ void k_cnt(const int* __restrict__ batch, int n) {
    int base = blockIdx.x * 256;
    int i = base + threadIdx.x;
    if (base >= n) return;
    int last = min(base + 255, n - 1);
    if (batch[base] == batch[last]) {
        if (threadIdx.x == 0) atomicAdd(&g_cnt[batch[base]], last - base + 1);
    } else if (i < n) {
        atomicAdd(&g_cnt[batch[i]], 1);
    }
}

// ---------------- in-degree count (int4 reads) ----------------
__global__ void k_count(const int* __restrict__ dst, int e) {
    int t = blockIdx.x * blockDim.x + threadIdx.x;
    int base = t * 4;
    if (base + 3 < e) {
        int4 d = *reinterpret_cast<const int4*>(dst + base);
        atomicAdd(&g_len[d.x], 1);
        atomicAdd(&g_len[d.y], 1);
        atomicAdd(&g_len[d.z], 1);
        atomicAdd(&g_len[d.w], 1);
    } else {
        for (int i = base; i < e; i++) atomicAdd(&g_len[dst[i]], 1);
    }
}

// ---------------- exclusive scan of g_len -> g_rowptr ----------------
__global__ void k_scan1(int n1) {
    __shared__ int sw[8];
    int gid = blockIdx.x * 256 + threadIdx.x;
    int lane = threadIdx.x & 31, wid = threadIdx.x >> 5;
    int v = (gid < n1) ? g_len[gid] : 0;
    int x = v;
    for (int o = 1; o < 32; o <<= 1) { int t = __shfl_up_sync(~0u, x, o); if (lane >= o) x += t; }
    if (lane == 31) sw[wid] = x;
    __syncthreads();
    if (wid == 0) {
        int y = (lane < 8) ? sw[lane] : 0;
        for (int o = 1; o < 8; o <<= 1) { int t = __shfl_up_sync(~0u, y, o); if (lane >= o) y += t; }
        if (lane < 8) sw[lane] = y;
    }
    __syncthreads();
    int off = wid ? sw[wid - 1] : 0;
    if (gid < n1) g_rowptr[gid] = x - v + off;
    if (threadIdx.x == 255) g_bsum[blockIdx.x] = off + x;
}
__global__ void k_scan2(int nb) {   // single block, 512 threads
    __shared__ int sw[16];
    int t = threadIdx.x, lane = t & 31, wid = t >> 5;
    int v = (t < nb) ? g_bsum[t] : 0;
    int x = v;
    for (int o = 1; o < 32; o <<= 1) { int q = __shfl_up_sync(~0u, x, o); if (lane >= o) x += q; }
    if (lane == 31) sw[wid] = x;
    __syncthreads();
    if (wid == 0) {
        int y = (lane < 16) ? sw[lane] : 0;
        for (int o = 1; o < 16; o <<= 1) { int q = __shfl_up_sync(~0u, y, o); if (lane >= o) y += q; }
        if (lane < 16) sw[lane] = y;
    }
    __syncthreads();
    int off = wid ? sw[wid - 1] : 0;
    if (t < nb) g_bsum[t] = x - v + off;   // exclusive
}
__global__ void k_scan3(int n1) {
    int gid = blockIdx.x * 256 + threadIdx.x;
    if (gid < n1) {
        int v = g_rowptr[gid] + g_bsum[blockIdx.x];
        g_rowptr[gid] = v;
        g_cur[gid] = v;   // absolute placement cursor
    }
}

// ---------------- place edges into CSR (src only) ----------------
__global__ void k_place(const int* __restrict__ src, const int* __restrict__ dst, int e) {
    int i = blockIdx.x * blockDim.x + threadIdx.x;
    if (i >= e) return;
    int d = dst[i];
    int pos = atomicAdd(&g_cur[d], 1);
    g_csr[pos] = src[i];
}

// ---------------- pad+pre-scale x: P[i,f] = dinv[i] * x[i,f], [N,32] ----------------
__global__ void k_pad(const float* __restrict__ x, float* __restrict__ P, int n) {
    int tid = blockIdx.x * blockDim.x + threadIdx.x;
    int i = tid >> 5, f = tid & 31;
    if (i >= n) return;
    float di = rsqrtf((float)(g_len[i] + 1));
    P[(size_t)i * 32 + f] = (f < IN_DIM) ? x[(size_t)i * IN_DIM + f] * di : 0.f;
}

// ---------------- pull F=32 fp32: out[i] = dinv_i*(sum in[j] + in[i]) (+b3/pool) ----
template<bool POOL>
__global__ void k_pull32(const float* __restrict__ in, float* __restrict__ out,
                         const float* __restrict__ b, const int* __restrict__ batch, int n) {
    int warp = (blockIdx.x * blockDim.x + threadIdx.x) >> 5;
    int lane = threadIdx.x & 31;
    if (warp >= n) return;
    int beg = g_rowptr[warp], end = g_rowptr[warp + 1];
    float dinv = rsqrtf((float)(end - beg + 1));
    float a0 = 0.f;
    int base = beg;
    for (; base + 32 <= end; base += 32) {
        int m = g_csr[base + lane];
#pragma unroll
        for (int j = 0; j < 32; j++) {
            int s = __shfl_sync(~0u, m, j);
            a0 += __ldg(&in[(size_t)s * 32 + lane]);
        }
    }
    int rem = end - base;
    if (rem > 0) {
        int m = (lane < rem) ? g_csr[base + lane] : 0;
        for (int j = 0; j < rem; j++) {
            int s = __shfl_sync(~0u, m, j);
            a0 += __ldg(&in[(size_t)s * 32 + lane]);
        }
    }
    a0 += in[(size_t)warp * 32 + lane];   // self-loop (pre-scaled input)
    a0 *= dinv;
    if (POOL) {
        float p0 = fmaxf(a0 + b[lane], 0.f);
        atomicAdd(&g_pool[batch[warp] * 32 + lane], p0);
    } else {
        out[(size_t)warp * 32 + lane] = a0;
    }
}

// ---------------- pull F=64 from fp16: one 128B half2 warp-load per edge ----------------
__global__ void k_pull64h(const __half* __restrict__ in, float* __restrict__ out, int n) {
    int warp = (blockIdx.x * blockDim.x + threadIdx.x) >> 5;
    int lane = threadIdx.x & 31;
    if (warp >= n) return;
    const __half2* in2 = reinterpret_cast<const __half2*>(in);
    int beg = g_rowptr[warp], end = g_rowptr[warp + 1];
    float dinv = rsqrtf((float)(end - beg + 1));
    float a0 = 0.f, a1 = 0.f;
    int base = beg;
    for (; base + 32 <= end; base += 32) {
        int m = g_csr[base + lane];
#pragma unroll
        for (int j = 0; j < 32; j++) {
            int s = __shfl_sync(~0u, m, j);
            float2 f = __half22float2(__ldg(&in2[(size_t)s * 32 + lane]));
            a0 += f.x;
            a1 += f.y;
        }
    }
    int rem = end - base;
    if (rem > 0) {
        int m = (lane < rem) ? g_csr[base + lane] : 0;
        for (int j = 0; j < rem; j++) {
            int s = __shfl_sync(~0u, m, j);
            float2 f = __half22float2(__ldg(&in2[(size_t)s * 32 + lane]));
            a0 += f.x;
            a1 += f.y;
        }
    }
    {   // self-loop
        float2 f = __half22float2(in2[(size_t)warp * 32 + lane]);
        a0 += f.x;
        a1 += f.y;
    }
    // features (2*lane, 2*lane+1) -> natural row order via float2 store
    reinterpret_cast<float2*>(out)[(size_t)warp * 32 + lane] = make_float2(a0 * dinv, a1 * dinv);
}

// ---------------- persistent dense: O = X @ W, epilogue (+b)(relu)(dinv)(half) ----------------
// Weights staged in smem ONCE per block; grid-stride over node tiles.
template<int K, int F, bool BIAS, bool RELU_OUT, bool SCALE, bool OHALF>
__global__ void k_gemm_p(const float* __restrict__ X, const float* __restrict__ W,
                         const float* __restrict__ b, void* __restrict__ Oout,
                         int n, int kreal, int ntiles) {
    constexpr int NPB = 256 / F;
    __shared__ float Wsh[K * F];
    __shared__ float Xsh[NPB * K];
    __shared__ float bsh[F];
    int tid = threadIdx.x;
    for (int idx = tid; idx < K * F; idx += 256) {
        int k = idx / F;
        Wsh[idx] = (k < kreal) ? W[idx] : 0.f;
    }
    if (BIAS && tid < F) bsh[tid] = b[tid];
    int il = tid / F, f = tid % F;
    for (int tile = blockIdx.x; tile < ntiles; tile += gridDim.x) {
        int base = tile * NPB;
        __syncthreads();   // also orders Wsh before first use / Xsh reuse
        for (int idx = tid; idx < NPB * K; idx += 256) {
            int node = base + idx / K;
            Xsh[idx] = (node < n) ? X[(size_t)node * K + idx % K] : 0.f;
        }
        __syncthreads();
        int node = base + il;
        if (node < n) {
            float acc = 0.f;
#pragma unroll
            for (int k = 0; k < K; k++)
                acc = fmaf(Xsh[il * K + k], Wsh[k * F + f], acc);
            if (BIAS) acc += bsh[f];
            if (RELU_OUT) acc = fmaxf(acc, 0.f);
            if (SCALE) acc *= rsqrtf((float)(g_len[node] + 1));
            if (OHALF) ((__half*)Oout)[(size_t)node * F + f] = __float2half_rn(acc);
            else       ((float*)Oout)[(size_t)node * F + f] = acc;
        }
    }
}

// ---------------- fused persistent double GEMM: O = dinv .* (relu(X@W2+b2) @ W3) ----------------
__global__ void k_gemm2_p(const float* __restrict__ X, const float* __restrict__ W2,
                          const float* __restrict__ b2, const float* __restrict__ W3,
                          float* __restrict__ O, int n, int ntiles) {
    __shared__ float W2s[64 * 64];
    __shared__ float W3s[64 * 32];
    __shared__ float b2s[64];
    __shared__ float Xs[4 * 64];
    __shared__ float R2s[4 * 64];
    int tid = threadIdx.x;
    for (int i = tid; i < 64 * 64; i += 256) W2s[i] = W2[i];
    for (int i = tid; i < 64 * 32; i += 256) W3s[i] = W3[i];
    if (tid < 64) b2s[tid] = b2[tid];
    int il = tid >> 6, f = tid & 63;
    for (int tile = blockIdx.x; tile < ntiles; tile += gridDim.x) {
        int base = tile * 4;
        __syncthreads();
        for (int idx = tid; idx < 4 * 64; idx += 256) {
            int node = base + (idx >> 6);
            Xs[idx] = (node < n) ? X[(size_t)node * 64 + (idx & 63)] : 0.f;
        }
        __syncthreads();
        {   // r2 = relu(X@W2 + b2)
            float acc = 0.f;
#pragma unroll
            for (int k = 0; k < 64; k++)
                acc = fmaf(Xs[il * 64 + k], W2s[k * 64 + f], acc);
            R2s[il * 64 + f] = fmaxf(acc + b2s[f], 0.f);
        }
        __syncthreads();
        if (tid < 128) {   // s2 = dinv .* (r2 @ W3)
            int il2 = tid >> 5, f2 = tid & 31;
            int node = base + il2;
            if (node < n) {
                float acc = 0.f;
#pragma unroll
                for (int k = 0; k < 64; k++)
                    acc = fmaf(R2s[il2 * 64 + k], W3s[k * 32 + f2], acc);
                O[(size_t)node * 32 + f2] = acc * rsqrtf((float)(g_len[node] + 1));
            }
        }
    }
}

// ---------------- MLP head ----------------
__global__ void k_head(const float* __restrict__ Wh1, const float* __restrict__ bh1,
                       const float* __restrict__ Wh2, const float* __restrict__ bh2,
                       float* __restrict__ y, int G) {
    __shared__ float W1s[32 * 32], b1s[32], W2s[32];
    int t = threadIdx.x;
    for (int idx = t; idx < 1024; idx += blockDim.x) W1s[idx] = Wh1[idx];
    if (t < 32) { b1s[t] = bh1[t]; W2s[t] = Wh2[t]; }
    __syncthreads();
    if (t >= G) return;
    float inv = 1.f / fmaxf((float)g_cnt[t], 1.f);
    float row[32];
#pragma unroll
    for (int k = 0; k < 32; k++) row[k] = g_pool[t * 32 + k] * inv;
    float acc = bh2[0];
#pragma unroll
    for (int j = 0; j < 32; j++) {
        float s = b1s[j];
#pragma unroll
        for (int k = 0; k < 32; k++) s = fmaf(row[k], W1s[k * 32 + j], s);
        acc = fmaf(fmaxf(s, 0.f), W2s[j], acc);
    }
    y[t] = acc;
}

extern "C" void kernel_launch(void* const* d_in, const int* in_sizes, int n_in,
                              void* d_out, int out_size) {
    const float* x   = (const float*)d_in[0];
    const int*   ei  = (const int*)d_in[1];
    const int*   bat = (const int*)d_in[2];
    const float* W1  = (const float*)d_in[3];
    const float* b1  = (const float*)d_in[4];
    const float* W2  = (const float*)d_in[5];
    const float* b2  = (const float*)d_in[6];
    const float* W3  = (const float*)d_in[7];
    const float* b3  = (const float*)d_in[8];
    const float* Wh1 = (const float*)d_in[9];
    const float* bh1 = (const float*)d_in[10];
    const float* Wh2 = (const float*)d_in[11];
    const float* bh2 = (const float*)d_in[12];
    float* y = (float*)d_out;

    int n = in_sizes[0] / IN_DIM;
    int e = in_sizes[1] / 2;
    int G = out_size;
    int n1 = n + 1;
    const int* src = ei;
    const int* dst = ei + e;

    float *A, *B, *C;
    __half* H;
    cudaGetSymbolAddress((void**)&A, g_bufA);
    cudaGetSymbolAddress((void**)&B, g_bufB);
    cudaGetSymbolAddress((void**)&C, g_bufC);
    cudaGetSymbolAddress((void**)&H, g_hbuf);

    const int T = 256;
    auto blk = [](long long w, int t) { return (int)((w + t - 1) / t); };
    int scan_blocks = blk(n1, 256);
    const int PGRID = 1480;   // persistent gemm grid (~10 blocks/SM)

    // ---- CSR build (counting sort by dst, src-only payload) ----
    k_init <<<blk(n1, T), T>>>(n1, G);
    k_cnt  <<<blk(n, T), T>>>(bat, n);
    k_count<<<blk((e + 3) / 4, T), T>>>(dst, e);
    k_scan1<<<scan_blocks, 256>>>(n1);
    k_scan2<<<1, 512>>>(scan_blocks);
    k_scan3<<<scan_blocks, 256>>>(n1);
    k_place<<<blk(e, T), T>>>(src, dst, e);

    // ---- layer pipeline, activations pre-scaled by dinv ----
    // P = dinv .* pad(x) -> A[N,32]
    k_pad<<<blk((long long)n * 32, T), T>>>(x, A, n);
    // agg1 = dinv.*(gather-sum P + P) -> C[N,32]
    k_pull32<false><<<blk((long long)n * 32, T), T>>>(A, C, nullptr, nullptr, n);
    // s1 = half( dinv .* relu(agg1@W1 + b1) ) -> H[N,64] fp16
    {
        int ntiles = blk(n, 4);
        k_gemm_p<32, 64, true, true, true, true><<<min(PGRID, ntiles), 256>>>(C, W1, b1, H, n, IN_DIM, ntiles);
    }
    // agg2 = dinv.*(gather-sum s1 + s1) -> A[N,64] fp32
    k_pull64h<<<blk((long long)n * 32, T), T>>>(H, A, n);
    // s2 = dinv .* (relu(agg2@W2+b2) @ W3) -> B[N,32]   (fused double GEMM)
    {
        int ntiles = blk(n, 4);
        k_gemm2_p<<<min(PGRID, ntiles), 256>>>(A, W2, b2, W3, B, n, ntiles);
    }
    // out3 = dinv.*(gather-sum s2 + s2) + b3 ; pool += relu(out3)   (fused)
    k_pull32<true><<<blk((long long)n * 32, T), T>>>(B, nullptr, b3, bat, n);

    // ---- head ----
    k_head<<<1, 256>>>(Wh1, bh1, Wh2, bh2, y, G);
}

// round 14
// speedup vs baseline: 1.4860x; 1.0553x over previous
#include <cuda_runtime.h>
#include <cuda_fp16.h>

#define NMAX 100000
#define EMAX 3200000
#define GMAXG 256
#define IN_DIM 25

// Scratch
__device__ float  g_bufA[NMAX * 64];
__device__ float  g_bufB[NMAX * 64];
__device__ __half g_hbuf[NMAX * 64];
__device__ int    g_csr[EMAX];        // src indices grouped by dst
__device__ int    g_rowptr[NMAX + 2];
__device__ int    g_len[NMAX + 1];
__device__ int    g_cur[NMAX + 1];
__device__ int    g_bsum[512];
__device__ float  g_pool[GMAXG * 32];
__device__ int    g_cnt[GMAXG];

// ---------------- init: zero len + cnt ----------------
__global__ void k_init(int n1, int G) {
    int i = blockIdx.x * blockDim.x + threadIdx.x;
    if (i < n1) g_len[i] = 0;
    if (i < G) g_cnt[i] = 0;
}

// ---------------- merged: per-graph node counts + in-degree count ----------------
__global__ void k_cntcount(const int* __restrict__ batch, const int* __restrict__ dst,
                           int n, int e) {
    int t = blockIdx.x * blockDim.x + threadIdx.x;
    // degree count (int4)
    int base4 = t * 4;
    if (base4 + 3 < e) {
        int4 d = *reinterpret_cast<const int4*>(dst + base4);
        atomicAdd(&g_len[d.x], 1);
        atomicAdd(&g_len[d.y], 1);
        atomicAdd(&g_len[d.z], 1);
        atomicAdd(&g_len[d.w], 1);
    } else {
        for (int i = base4; i < e; i++) atomicAdd(&g_len[dst[i]], 1);
    }
    // batch counts (sorted batch, blockwise-uniform fast path)
    int nb = blockIdx.x * 256;
    if (nb < n) {
        int last = min(nb + 255, n - 1);
        if (batch[nb] == batch[last]) {
            if (threadIdx.x == 0) atomicAdd(&g_cnt[batch[nb]], last - nb + 1);
        } else if (t < n) {
            atomicAdd(&g_cnt[batch[t]], 1);
        }
    }
}

// ---------------- exclusive scan of g_len -> g_rowptr ----------------
__global__ void k_scan1(int n1) {
    __shared__ int sw[8];
    int gid = blockIdx.x * 256 + threadIdx.x;
    int lane = threadIdx.x & 31, wid = threadIdx.x >> 5;
    int v = (gid < n1) ? g_len[gid] : 0;
    int x = v;
    for (int o = 1; o < 32; o <<= 1) { int t = __shfl_up_sync(~0u, x, o); if (lane >= o) x += t; }
    if (lane == 31) sw[wid] = x;
    __syncthreads();
    if (wid == 0) {
        int y = (lane < 8) ? sw[lane] : 0;
        for (int o = 1; o < 8; o <<= 1) { int t = __shfl_up_sync(~0u, y, o); if (lane >= o) y += t; }
        if (lane < 8) sw[lane] = y;
    }
    __syncthreads();
    int off = wid ? sw[wid - 1] : 0;
    if (gid < n1) g_rowptr[gid] = x - v + off;
    if (threadIdx.x == 255) g_bsum[blockIdx.x] = off + x;
}
__global__ void k_scan2(int nb, int G) {   // single block, 512 threads (+ pool zeroing)
    __shared__ int sw[16];
    int t = threadIdx.x, lane = t & 31, wid = t >> 5;
    for (int i = t; i < G * 32; i += 512) g_pool[i] = 0.f;   // zero pool (used much later)
    int v = (t < nb) ? g_bsum[t] : 0;
    int x = v;
    for (int o = 1; o < 32; o <<= 1) { int q = __shfl_up_sync(~0u, x, o); if (lane >= o) x += q; }
    if (lane == 31) sw[wid] = x;
    __syncthreads();
    if (wid == 0) {
        int y = (lane < 16) ? sw[lane] : 0;
        for (int o = 1; o < 16; o <<= 1) { int q = __shfl_up_sync(~0u, y, o); if (lane >= o) y += q; }
        if (lane < 16) sw[lane] = y;
    }
    __syncthreads();
    int off = wid ? sw[wid - 1] : 0;
    if (t < nb) g_bsum[t] = x - v + off;   // exclusive
}
__global__ void k_scan3(int n1) {
    int gid = blockIdx.x * 256 + threadIdx.x;
    if (gid < n1) {
        int v = g_rowptr[gid] + g_bsum[blockIdx.x];
        g_rowptr[gid] = v;
        g_cur[gid] = v;   // absolute placement cursor
    }
}

// ---------------- merged: place edges into CSR + pad/pre-scale x ----------------
__global__ void k_placepad(const int* __restrict__ src, const int* __restrict__ dst,
                           const float* __restrict__ x, float* __restrict__ P,
                           int e, int n) {
    int i = blockIdx.x * blockDim.x + threadIdx.x;
    if (i < e) {
        int d = dst[i];
        int pos = atomicAdd(&g_cur[d], 1);
        g_csr[pos] = src[i];
    }
    // pad: P[node,f] = dinv[node] * x[node,f]  (f >= IN_DIM -> 0)
    int node = i >> 5, f = i & 31;
    if (node < n) {
        float di = rsqrtf((float)(g_len[node] + 1));
        P[(size_t)node * 32 + f] = (f < IN_DIM) ? x[(size_t)node * IN_DIM + f] * di : 0.f;
    }
}

// ---------------- FUSED pull32 + GEMM(32->64): H = half(dinv.*relu(agg1@W1+b1)) ----------------
// Persistent grid; W1 staged in smem once per block. agg1 computed in-warp (feature=lane),
// then the tiny GEMM done via shfl-broadcast + LDS.64, lane emits features (2l, 2l+1) as half2.
__global__ void k_pullgemm1(const float* __restrict__ in, const float* __restrict__ W1,
                            const float* __restrict__ b1, __half* __restrict__ H,
                            int n, int totalwarps) {
    __shared__ float Wsh[32 * 64];
    __shared__ float bsh[64];
    int tid = threadIdx.x;
    for (int idx = tid; idx < 32 * 64; idx += 256) {
        int k = idx >> 6;
        Wsh[idx] = (k < IN_DIM) ? W1[idx] : 0.f;
    }
    if (tid < 64) bsh[tid] = b1[tid];
    __syncthreads();
    const float2* Wsh2 = reinterpret_cast<const float2*>(Wsh);
    const float2* bsh2 = reinterpret_cast<const float2*>(bsh);
    int warp0 = (blockIdx.x * 256 + tid) >> 5;
    int lane = tid & 31;

    for (int node = warp0; node < n; node += totalwarps) {
        int beg = g_rowptr[node], end = g_rowptr[node + 1];
        float dinv = rsqrtf((float)(end - beg + 1));
        float aE = 0.f, aO = 0.f;
        int base = beg;
        for (; base + 32 <= end; base += 32) {
            int m = g_csr[base + lane];
#pragma unroll
            for (int j = 0; j < 32; j += 2) {
                int s0 = __shfl_sync(~0u, m, j);
                int s1 = __shfl_sync(~0u, m, j + 1);
                aE += __ldg(&in[(size_t)s0 * 32 + lane]);
                aO += __ldg(&in[(size_t)s1 * 32 + lane]);
            }
        }
        int rem = end - base;
        if (rem > 0) {
            int m = (lane < rem) ? g_csr[base + lane] : 0;
            for (int j = 0; j < rem; j++) {
                int s = __shfl_sync(~0u, m, j);
                if (j & 1) aO += __ldg(&in[(size_t)s * 32 + lane]);
                else       aE += __ldg(&in[(size_t)s * 32 + lane]);
            }
        }
        float a = (aE + aO + in[(size_t)node * 32 + lane]) * dinv;   // agg1 (feature=lane)
        // s1 = dinv .* relu(agg1 @ W1 + b1)
        float c0 = 0.f, c1 = 0.f;
#pragma unroll
        for (int k = 0; k < 32; k++) {
            float v = __shfl_sync(~0u, a, k);
            float2 w = Wsh2[k * 32 + lane];
            c0 = fmaf(v, w.x, c0);
            c1 = fmaf(v, w.y, c1);
        }
        float2 bb = bsh2[lane];
        c0 = fmaxf(c0 + bb.x, 0.f) * dinv;
        c1 = fmaxf(c1 + bb.y, 0.f) * dinv;
        reinterpret_cast<__half2*>(H)[(size_t)node * 32 + lane] = __floats2half2_rn(c0, c1);
    }
}

// ---------------- pull F=64 from fp16: one 128B half2 warp-load per edge ----------------
__global__ void k_pull64h(const __half* __restrict__ in, float* __restrict__ out, int n) {
    int warp = (blockIdx.x * blockDim.x + threadIdx.x) >> 5;
    int lane = threadIdx.x & 31;
    if (warp >= n) return;
    const __half2* in2 = reinterpret_cast<const __half2*>(in);
    int beg = g_rowptr[warp], end = g_rowptr[warp + 1];
    float dinv = rsqrtf((float)(end - beg + 1));
    float a0 = 0.f, a1 = 0.f, a2 = 0.f, a3 = 0.f;
    int base = beg;
    for (; base + 32 <= end; base += 32) {
        int m = g_csr[base + lane];
#pragma unroll
        for (int j = 0; j < 32; j += 2) {
            int s0 = __shfl_sync(~0u, m, j);
            int s1 = __shfl_sync(~0u, m, j + 1);
            float2 f0 = __half22float2(__ldg(&in2[(size_t)s0 * 32 + lane]));
            float2 f1 = __half22float2(__ldg(&in2[(size_t)s1 * 32 + lane]));
            a0 += f0.x; a1 += f0.y;
            a2 += f1.x; a3 += f1.y;
        }
    }
    int rem = end - base;
    if (rem > 0) {
        int m = (lane < rem) ? g_csr[base + lane] : 0;
        for (int j = 0; j < rem; j++) {
            int s = __shfl_sync(~0u, m, j);
            float2 f = __half22float2(__ldg(&in2[(size_t)s * 32 + lane]));
            if (j & 1) { a2 += f.x; a3 += f.y; }
            else       { a0 += f.x; a1 += f.y; }
        }
    }
    {   // self-loop
        float2 f = __half22float2(in2[(size_t)warp * 32 + lane]);
        a0 += f.x; a1 += f.y;
    }
    reinterpret_cast<float2*>(out)[(size_t)warp * 32 + lane] =
        make_float2((a0 + a2) * dinv, (a1 + a3) * dinv);
}

// ---------------- fused persistent double GEMM: O = dinv .* (relu(X@W2+b2) @ W3) ----------------
__global__ void k_gemm2_p(const float* __restrict__ X, const float* __restrict__ W2,
                          const float* __restrict__ b2, const float* __restrict__ W3,
                          float* __restrict__ O, int n, int ntiles) {
    __shared__ float W2s[64 * 64];
    __shared__ float W3s[64 * 32];
    __shared__ float b2s[64];
    __shared__ float Xs[4 * 64];
    __shared__ float R2s[4 * 64];
    int tid = threadIdx.x;
    for (int i = tid; i < 64 * 64; i += 256) W2s[i] = W2[i];
    for (int i = tid; i < 64 * 32; i += 256) W3s[i] = W3[i];
    if (tid < 64) b2s[tid] = b2[tid];
    int il = tid >> 6, f = tid & 63;
    for (int tile = blockIdx.x; tile < ntiles; tile += gridDim.x) {
        int base = tile * 4;
        __syncthreads();
        for (int idx = tid; idx < 4 * 64; idx += 256) {
            int node = base + (idx >> 6);
            Xs[idx] = (node < n) ? X[(size_t)node * 64 + (idx & 63)] : 0.f;
        }
        __syncthreads();
        {   // r2 = relu(X@W2 + b2)
            float acc = 0.f;
#pragma unroll
            for (int k = 0; k < 64; k++)
                acc = fmaf(Xs[il * 64 + k], W2s[k * 64 + f], acc);
            R2s[il * 64 + f] = fmaxf(acc + b2s[f], 0.f);
        }
        __syncthreads();
        if (tid < 128) {   // s2 = dinv .* (r2 @ W3)
            int il2 = tid >> 5, f2 = tid & 31;
            int node = base + il2;
            if (node < n) {
                float acc = 0.f;
#pragma unroll
                for (int k = 0; k < 64; k++)
                    acc = fmaf(R2s[il2 * 64 + k], W3s[k * 32 + f2], acc);
                O[(size_t)node * 32 + f2] = acc * rsqrtf((float)(g_len[node] + 1));
            }
        }
    }
}

// ---------------- pull F=32 fp32 + fused pool epilogue ----------------
__global__ void k_pull32pool(const float* __restrict__ in, const float* __restrict__ b,
                             const int* __restrict__ batch, int n) {
    int warp = (blockIdx.x * blockDim.x + threadIdx.x) >> 5;
    int lane = threadIdx.x & 31;
    if (warp >= n) return;
    int beg = g_rowptr[warp], end = g_rowptr[warp + 1];
    float dinv = rsqrtf((float)(end - beg + 1));
    float aE = 0.f, aO = 0.f;
    int base = beg;
    for (; base + 32 <= end; base += 32) {
        int m = g_csr[base + lane];
#pragma unroll
        for (int j = 0; j < 32; j += 2) {
            int s0 = __shfl_sync(~0u, m, j);
            int s1 = __shfl_sync(~0u, m, j + 1);
            aE += __ldg(&in[(size_t)s0 * 32 + lane]);
            aO += __ldg(&in[(size_t)s1 * 32 + lane]);
        }
    }
    int rem = end - base;
    if (rem > 0) {
        int m = (lane < rem) ? g_csr[base + lane] : 0;
        for (int j = 0; j < rem; j++) {
            int s = __shfl_sync(~0u, m, j);
            if (j & 1) aO += __ldg(&in[(size_t)s * 32 + lane]);
            else       aE += __ldg(&in[(size_t)s * 32 + lane]);
        }
    }
    float a0 = (aE + aO + in[(size_t)warp * 32 + lane]) * dinv;
    float p0 = fmaxf(a0 + b[lane], 0.f);
    atomicAdd(&g_pool[batch[warp] * 32 + lane], p0);
}

// ---------------- MLP head ----------------
__global__ void k_head(const float* __restrict__ Wh1, const float* __restrict__ bh1,
                       const float* __restrict__ Wh2, const float* __restrict__ bh2,
                       float* __restrict__ y, int G) {
    __shared__ float W1s[32 * 32], b1s[32], W2s[32];
    int t = threadIdx.x;
    for (int idx = t; idx < 1024; idx += blockDim.x) W1s[idx] = Wh1[idx];
    if (t < 32) { b1s[t] = bh1[t]; W2s[t] = Wh2[t]; }
    __syncthreads();
    if (t >= G) return;
    float inv = 1.f / fmaxf((float)g_cnt[t], 1.f);
    float row[32];
#pragma unroll
    for (int k = 0; k < 32; k++) row[k] = g_pool[t * 32 + k] * inv;
    float acc = bh2[0];
#pragma unroll
    for (int j = 0; j < 32; j++) {
        float s = b1s[j];
#pragma unroll
        for (int k = 0; k < 32; k++) s = fmaf(row[k], W1s[k * 32 + j], s);
        acc = fmaf(fmaxf(s, 0.f), W2s[j], acc);
    }
    y[t] = acc;
}

extern "C" void kernel_launch(void* const* d_in, const int* in_sizes, int n_in,
                              void* d_out, int out_size) {
    const float* x   = (const float*)d_in[0];
    const int*   ei  = (const int*)d_in[1];
    const int*   bat = (const int*)d_in[2];
    const float* W1  = (const float*)d_in[3];
    const float* b1  = (const float*)d_in[4];
    const float* W2  = (const float*)d_in[5];
    const float* b2  = (const float*)d_in[6];
    const float* W3  = (const float*)d_in[7];
    const float* b3  = (const float*)d_in[8];
    const float* Wh1 = (const float*)d_in[9];
    const float* bh1 = (const float*)d_in[10];
    const float* Wh2 = (const float*)d_in[11];
    const float* bh2 = (const float*)d_in[12];
    float* y = (float*)d_out;

    int n = in_sizes[0] / IN_DIM;
    int e = in_sizes[1] / 2;
    int G = out_size;
    int n1 = n + 1;
    const int* src = ei;
    const int* dst = ei + e;

    float *A, *B;
    __half* H;
    cudaGetSymbolAddress((void**)&A, g_bufA);
    cudaGetSymbolAddress((void**)&B, g_bufB);
    cudaGetSymbolAddress((void**)&H, g_hbuf);

    const int T = 256;
    auto blk = [](long long w, int t) { return (int)((w + t - 1) / t); };
    int scan_blocks = blk(n1, 256);
    const int PGRID = 1480;

    // ---- CSR build (counting sort by dst) ----
    k_init    <<<blk(n1, T), T>>>(n1, G);
    {
        long long w = max((long long)blk(e, 4) , (long long)n);
        k_cntcount<<<blk(w, T), T>>>(bat, dst, n, e);
    }
    k_scan1<<<scan_blocks, 256>>>(n1);
    k_scan2<<<1, 512>>>(scan_blocks, G);
    k_scan3<<<scan_blocks, 256>>>(n1);
    {
        long long w = max((long long)e, (long long)n * 32);
        k_placepad<<<blk(w, T), T>>>(src, dst, x, A, e, n);
    }

    // ---- layer pipeline ----
    // fused: agg1 = dinv.*(gather P + P); s1 = half(dinv.*relu(agg1@W1+b1)) -> H[N,64]
    {
        int pg = min(PGRID, blk(n, 8));
        k_pullgemm1<<<pg, 256>>>(A, W1, b1, H, n, pg * 8);
    }
    // agg2 = dinv.*(gather s1 + s1) -> A[N,64] fp32
    k_pull64h<<<blk((long long)n * 32, T), T>>>(H, A, n);
    // s2 = dinv .* (relu(agg2@W2+b2) @ W3) -> B[N,32]
    {
        int ntiles = blk(n, 4);
        k_gemm2_p<<<min(PGRID, ntiles), 256>>>(A, W2, b2, W3, B, n, ntiles);
    }
    // out3 = dinv.*(gather s2 + s2) + b3 ; pool += relu(out3)
    k_pull32pool<<<blk((long long)n * 32, T), T>>>(B, b3, bat, n);

    // ---- head ----
    k_head<<<1, 256>>>(Wh1, bh1, Wh2, bh2, y, G);
}